// round 2
// baseline (speedup 1.0000x reference)
#include <cuda_runtime.h>
#include <cuda_bf16.h>

// TELIF: temporal-encoded LIF neuron scan.
//   tx : [T, B, N] float32   (T=512, B=64, N=1024)
//   TE : [N, T]    float32
//   out: [T, B, N] float32 spikes
//
// Per (b, n), sequential in t:
//   th = th + v*TE[n,t] - (th - THRESHOLD)*BETA
//   v  = v*DECAY*(1 - y) + x
//   y  = (v > th) ? 1 : 0

#define T_STEPS 512
#define B_DIM   64
#define N_DIM   1024
#define BN      (B_DIM * N_DIM)      // 65536
#define U       8                    // timesteps per buffer

#define REST      0.0f
#define DECAY     0.2f
#define THRESHOLD 0.3f
#define BETA      0.02f

// Transposed temporal encoding: TEt[t][n]  (2 MB static device scratch)
__device__ float g_TEt[T_STEPS * N_DIM];

// ---------------------------------------------------------------------------
// Pre-pass: transpose TE [N, T] -> g_TEt [T, N].
// ---------------------------------------------------------------------------
__global__ void transpose_te_kernel(const float* __restrict__ TE) {
    __shared__ float tile[32][33];
    const int tbase = blockIdx.x * 32;
    const int nbase = blockIdx.y * 32;

    #pragma unroll
    for (int r = threadIdx.y; r < 32; r += 8)
        tile[r][threadIdx.x] = TE[(nbase + r) * T_STEPS + tbase + threadIdx.x];
    __syncthreads();
    #pragma unroll
    for (int r = threadIdx.y; r < 32; r += 8)
        g_TEt[(tbase + r) * N_DIM + nbase + threadIdx.x] = tile[threadIdx.x][r];
}

// ---------------------------------------------------------------------------
// Main scan. One thread owns TWO adjacent (b,n) chains (float2), giving 2x
// ILP on the serial recurrence and 64-bit memory ops. Double buffering is
// written with compile-time buffer selection (chunk pairs) so all buffers
// stay in registers — no dynamic array indexing anywhere.
// ---------------------------------------------------------------------------
__device__ __forceinline__ void lif_step(float2 x, float2 te,
                                         float2& v, float2& y, float2& th,
                                         float2* out) {
    // th = th + v*te - (th - THRESHOLD)*BETA  ==  fma(v,te, fma(th,1-B, T*B))
    th.x = fmaf(v.x, te.x, fmaf(th.x, 1.0f - BETA, THRESHOLD * BETA));
    th.y = fmaf(v.y, te.y, fmaf(th.y, 1.0f - BETA, THRESHOLD * BETA));
    // v = (v*DECAY)*(1-y) + x
    v.x = fmaf(v.x * DECAY, 1.0f - y.x, x.x);
    v.y = fmaf(v.y * DECAY, 1.0f - y.y, x.y);
    y.x = (v.x > th.x) ? 1.0f : 0.0f;
    y.y = (v.y > th.y) ? 1.0f : 0.0f;
    *out = y;
}

__global__ void __launch_bounds__(64) telif_kernel(
    const float2* __restrict__ tx,     // [T][BN/2]
    float2* __restrict__ ty)           // [T][BN/2]
{
    const int g  = blockIdx.x * blockDim.x + threadIdx.x;   // float2 index in [0, BN/2)
    const int n2 = g & (N_DIM / 2 - 1);                     // float2 index within N
    const float2* te2 = reinterpret_cast<const float2*>(g_TEt);

    float2 v  = make_float2(REST, REST);
    float2 y  = make_float2(0.0f, 0.0f);
    float2 th = make_float2(THRESHOLD, THRESHOLD);

    float2 xa[U], ta[U], xb[U], tb[U];

    // prologue: prefetch chunk 0 into A
    #pragma unroll
    for (int u = 0; u < U; u++) {
        xa[u] = tx[u * (BN / 2) + g];
        ta[u] = te2[u * (N_DIM / 2) + n2];
    }

    #pragma unroll 1
    for (int tc = 0; tc < T_STEPS; tc += 2 * U) {
        // prefetch chunk tc+U into B
        #pragma unroll
        for (int u = 0; u < U; u++) {
            xb[u] = tx[(tc + U + u) * (BN / 2) + g];
            tb[u] = te2[(tc + U + u) * (N_DIM / 2) + n2];
        }
        // compute chunk tc from A
        #pragma unroll
        for (int u = 0; u < U; u++)
            lif_step(xa[u], ta[u], v, y, th, &ty[(tc + u) * (BN / 2) + g]);

        // prefetch chunk tc+2U into A (guarded — last pair has none)
        if (tc + 2 * U < T_STEPS) {
            #pragma unroll
            for (int u = 0; u < U; u++) {
                xa[u] = tx[(tc + 2 * U + u) * (BN / 2) + g];
                ta[u] = te2[(tc + 2 * U + u) * (N_DIM / 2) + n2];
            }
        }
        // compute chunk tc+U from B
        #pragma unroll
        for (int u = 0; u < U; u++)
            lif_step(xb[u], tb[u], v, y, th, &ty[(tc + U + u) * (BN / 2) + g]);
    }
}

// ---------------------------------------------------------------------------
extern "C" void kernel_launch(void* const* d_in, const int* in_sizes, int n_in,
                              void* d_out, int out_size) {
    const float* tx = (const float*)d_in[0];   // [T, B, N]
    const float* TE = (const float*)d_in[1];   // [N, T]
    float* ty = (float*)d_out;                 // [T, B, N]
    (void)in_sizes; (void)n_in; (void)out_size;

    dim3 tgrid(T_STEPS / 32, N_DIM / 32);
    dim3 tblock(32, 8);
    transpose_te_kernel<<<tgrid, tblock>>>(TE);

    telif_kernel<<<(BN / 2) / 64, 64>>>(
        reinterpret_cast<const float2*>(tx),
        reinterpret_cast<float2*>(ty));
}

// round 4
// speedup vs baseline: 1.8765x; 1.8765x over previous
#include <cuda_runtime.h>
#include <cuda_bf16.h>

// TELIF: temporal-encoded LIF neuron scan.
//   tx : [T, B, N] float32   (T=512, B=64, N=1024)
//   TE : [N, T]    float32
//   out: [T, B, N] float32 spikes
//
// Per (b, n), sequential in t:
//   th = th + v*TE[n,t] - (th - THRESHOLD)*BETA
//   v  = v*DECAY*(1 - y) + x
//   y  = (v > th) ? 1 : 0

#define T_STEPS 512
#define B_DIM   64
#define N_DIM   1024
#define BN      (B_DIM * N_DIM)      // 65536
#define U       4                    // timesteps per chunk
#define NCHUNK  (T_STEPS / U)        // 128

#define REST      0.0f
#define DECAY     0.2f
#define THRESHOLD 0.3f
#define BETA      0.02f

// Transposed temporal encoding: TEt[t][n]  (2 MB static device scratch)
__device__ float g_TEt[T_STEPS * N_DIM];

// ---------------------------------------------------------------------------
// Pre-pass: transpose TE [N, T] -> g_TEt [T, N].
// ---------------------------------------------------------------------------
__global__ void transpose_te_kernel(const float* __restrict__ TE) {
    __shared__ float tile[32][33];
    const int tbase = blockIdx.x * 32;
    const int nbase = blockIdx.y * 32;

    #pragma unroll
    for (int r = threadIdx.y; r < 32; r += 8)
        tile[r][threadIdx.x] = TE[(nbase + r) * T_STEPS + tbase + threadIdx.x];
    __syncthreads();
    #pragma unroll
    for (int r = threadIdx.y; r < 32; r += 8)
        g_TEt[(tbase + r) * N_DIM + nbase + threadIdx.x] = tile[threadIdx.x][r];
}

// ---------------------------------------------------------------------------
// Main scan. One thread per (b,n) chain (65536 threads -> ~14 warps/SM).
// Software pipeline: 4 register buffers of U=4 timesteps, uniform prefetch
// distance of 3 chunk-periods, all buffer indices compile-time constants.
// tx is streamed (__ldcs), ty is streamed out (__stcs), TE stays L2-cached.
// ---------------------------------------------------------------------------

// load chunk c into buffer (xq, tq)
#define LOAD_CHUNK(xq, tq, c)                                         \
    {                                                                 \
        _Pragma("unroll")                                             \
        for (int u = 0; u < U; u++) {                                 \
            xq[u] = __ldcs(&tx[((c) * U + u) * BN + g]);              \
            tq[u] = g_TEt[((c) * U + u) * N_DIM + n];                 \
        }                                                             \
    }

// compute chunk c from buffer (xq, tq)  — arithmetic form kept identical to
// reference (this form measured rel_err == 0.0)
#define COMPUTE_CHUNK(xq, tq, c)                                      \
    {                                                                 \
        _Pragma("unroll")                                             \
        for (int u = 0; u < U; u++) {                                 \
            const float x  = xq[u];                                   \
            const float te = tq[u];                                   \
            th = th + v * te - (th - THRESHOLD) * BETA;               \
            v  = v * DECAY * (1.0f - y) + x;                          \
            y  = (v > th) ? 1.0f : 0.0f;                              \
            __stcs(&ty[((c) * U + u) * BN + g], y);                   \
        }                                                             \
    }

__global__ void __launch_bounds__(128) telif_kernel(
    const float* __restrict__ tx,
    float* __restrict__ ty)
{
    const int g = blockIdx.x * blockDim.x + threadIdx.x;  // g = b*N + n
    const int n = g & (N_DIM - 1);

    float v  = REST;
    float y  = 0.0f;
    float th = THRESHOLD;

    float xA[U], tA[U], xB[U], tB[U], xC[U], tC[U], xD[U], tD[U];

    // prologue: chunks 0,1,2 into A,B,C
    LOAD_CHUNK(xA, tA, 0)
    LOAD_CHUNK(xB, tB, 1)
    LOAD_CHUNK(xC, tC, 2)

    #pragma unroll 1
    for (int c = 0; c < NCHUNK; c += 4) {
        LOAD_CHUNK(xD, tD, c + 3)
        COMPUTE_CHUNK(xA, tA, c)
        if (c + 4 < NCHUNK) LOAD_CHUNK(xA, tA, c + 4)
        COMPUTE_CHUNK(xB, tB, c + 1)
        if (c + 5 < NCHUNK) LOAD_CHUNK(xB, tB, c + 5)
        COMPUTE_CHUNK(xC, tC, c + 2)
        if (c + 6 < NCHUNK) LOAD_CHUNK(xC, tC, c + 6)
        COMPUTE_CHUNK(xD, tD, c + 3)
    }
}

// ---------------------------------------------------------------------------
extern "C" void kernel_launch(void* const* d_in, const int* in_sizes, int n_in,
                              void* d_out, int out_size) {
    const float* tx = (const float*)d_in[0];   // [T, B, N]
    const float* TE = (const float*)d_in[1];   // [N, T]
    float* ty = (float*)d_out;                 // [T, B, N]
    (void)in_sizes; (void)n_in; (void)out_size;

    dim3 tgrid(T_STEPS / 32, N_DIM / 32);
    dim3 tblock(32, 8);
    transpose_te_kernel<<<tgrid, tblock>>>(TE);

    telif_kernel<<<BN / 128, 128>>>(tx, ty);
}